// round 1
// baseline (speedup 1.0000x reference)
#include <cuda_runtime.h>
#include <math.h>

#define VOCAB 50000
#define EMB 50
#define B 256
#define S 2048
#define L1OUT (S + 6)      // 2054 conv1 output length
#define NEG_INF (-1e30f)

// Scratch (device globals are the allowed way to get scratch)
__device__ __align__(16) float g_T[VOCAB * 8];   // T[v][0..6] dot(emb[v], wmean[kw]), padded to 8
__device__ float g_part[B];                       // per-batch-row dense output

// ---------------------------------------------------------------------------
// Kernel A: T[v][kw] = dot(emb[v], wmean[kw]),  wmean[kw][cin] = mean_c W1
// ---------------------------------------------------------------------------
__global__ void buildT_kernel(const float* __restrict__ emb,
                              const float* __restrict__ W1) {
    __shared__ float wm[7 * 50];
    int tid = threadIdx.x;
    for (int i = tid; i < 350; i += 256) {
        float s = 0.f;
        #pragma unroll
        for (int c = 0; c < 6; c++) s += W1[i * 6 + c];
        wm[i] = s * (1.f / 6.f);
    }
    __syncthreads();

    int v = blockIdx.x * 256 + tid;
    if (v >= VOCAB) return;
    const float* er = emb + (size_t)v * EMB;
    float acc[7] = {0.f, 0.f, 0.f, 0.f, 0.f, 0.f, 0.f};
    for (int cin = 0; cin < EMB; cin++) {
        float e = er[cin];
        #pragma unroll
        for (int kw = 0; kw < 7; kw++) acc[kw] += e * wm[kw * 50 + cin];
    }
    float4* d = (float4*)(g_T + (size_t)v * 8);
    d[0] = make_float4(acc[0], acc[1], acc[2], acc[3]);
    d[1] = make_float4(acc[4], acc[5], acc[6], 0.f);
}

// ---------------------------------------------------------------------------
// Kernel B: one CTA per batch row. Excitements -> top8 -> conv1@8 -> sigmoid
//           -> pad -> conv2 -> top4 -> mean -> dense. Writes g_part[b].
// ---------------------------------------------------------------------------
__global__ void __launch_bounds__(256) dcnn_row_kernel(
    const int*   __restrict__ x,
    const float* __restrict__ emb,
    const float* __restrict__ W1, const float* __restrict__ b1,
    const float* __restrict__ W2, const float* __restrict__ b2,
    const float* __restrict__ Wd, const float* __restrict__ bd) {

    extern __shared__ float sm[];
    float* sT   = sm;               // 2048*7 = 14336 floats (T values per token)
    float* exc  = sT + 14336;       // 2056 floats (2054 used)
    float* rv   = exc + 2056;       // 256
    int*   ri   = (int*)(rv + 256); // 256
    int*   idx8 = ri + 256;         // 8
    float* s1p  = (float*)(idx8 + 8); // 16*6 = 96 (padded sigmoid(conv1) rows)
    float* out2 = s1p + 96;         // 12*14 = 168
    float* exc2 = out2 + 168;       // 12
    int*   j4   = (int*)(exc2 + 12);// 4
    float* mbuf = (float*)(j4 + 4); // 14
    float* embw = sT;               // alias: 8*7*50 = 2800 floats, reused after phase 3

    const int tid = threadIdx.x;
    const int b   = blockIdx.x;
    const int* xr = x + (size_t)b * S;

    // ---- Phase 1: stage T rows for all 2048 tokens (stride-7: conflict-free)
    for (int p = tid; p < S; p += 256) {
        int tok = xr[p];
        const float4* tp = (const float4*)(g_T + (size_t)tok * 8);
        float4 a = tp[0];
        float4 c = tp[1];
        float* d = sT + p * 7;
        d[0] = a.x; d[1] = a.y; d[2] = a.z; d[3] = a.w;
        d[4] = c.x; d[5] = c.y; d[6] = c.z;
    }
    __syncthreads();

    // ---- Phase 2: excitements. output t uses original positions t-6 .. t
    for (int t = tid; t < L1OUT; t += 256) {
        float s = 0.f;
        int p0 = t - 6;
        #pragma unroll
        for (int kw = 0; kw < 7; kw++) {
            int p = p0 + kw;
            if (p >= 0 && p < S) s += sT[p * 7 + kw];
        }
        exc[t] = s;
    }
    __syncthreads();

    // ---- Phase 3: top-8 (descending value, ties -> lower index) = lax.top_k
    for (int r = 0; r < 8; r++) {
        float bv = NEG_INF; int bi = 0x7fffffff;
        for (int t = tid; t < L1OUT; t += 256) {
            float v = exc[t];
            if (v > bv || (v == bv && t < bi)) { bv = v; bi = t; }
        }
        rv[tid] = bv; ri[tid] = bi;
        __syncthreads();
        for (int s = 128; s > 0; s >>= 1) {
            if (tid < s) {
                float v2 = rv[tid + s]; int i2 = ri[tid + s];
                if (v2 > rv[tid] || (v2 == rv[tid] && i2 < ri[tid])) {
                    rv[tid] = v2; ri[tid] = i2;
                }
            }
            __syncthreads();
        }
        if (tid == 0) { idx8[r] = ri[0]; exc[ri[0]] = NEG_INF; }
        __syncthreads();
    }

    // ---- Phase 4: stage embedding windows for the 8 positions, zero s1p
    for (int e = tid; e < 8 * 350; e += 256) {
        int i = e / 350, rr = e % 350;
        int kw = rr / 50, cin = rr % 50;
        int p = idx8[i] - 6 + kw;
        float v = 0.f;
        if (p >= 0 && p < S) v = emb[(size_t)xr[p] * EMB + cin];
        embw[e] = v;
    }
    if (tid < 96) s1p[tid] = 0.f;   // zero-pad rows (0..3, 12..15 stay zero)
    __syncthreads();

    // conv1 at the 8 positions + bias + sigmoid -> s1p rows 4..11
    if (tid < 48) {
        int i = tid / 6, c = tid % 6;
        float acc = b1[c];
        const float* ew = embw + i * 350;
        #pragma unroll 7
        for (int rr = 0; rr < 350; rr++) acc += ew[rr] * W1[rr * 6 + c];
        s1p[(4 + i) * 6 + c] = 1.f / (1.f + expf(-acc));
    }
    __syncthreads();

    // ---- Phase 5: conv2 over the 16-long padded sequence -> [12,14]
    if (tid < 12 * 14) {
        int t2 = tid / 14, c2 = tid % 14;
        float acc = b2[c2];
        #pragma unroll
        for (int kw2 = 0; kw2 < 5; kw2++)
            #pragma unroll
            for (int cin = 0; cin < 6; cin++)
                acc += s1p[(t2 + kw2) * 6 + cin] * W2[(kw2 * 6 + cin) * 14 + c2];
        out2[t2 * 14 + c2] = acc;
    }
    __syncthreads();

    if (tid < 12) {
        float s = 0.f;
        #pragma unroll
        for (int c = 0; c < 14; c++) s += out2[tid * 14 + c];
        exc2[tid] = s;   // ranking key (mean scale / bias const irrelevant)
    }
    __syncthreads();

    if (tid == 0) {
        bool used[12];
        #pragma unroll
        for (int t = 0; t < 12; t++) used[t] = false;
        for (int r = 0; r < 4; r++) {
            float bv = NEG_INF; int bi = 0;
            for (int t = 0; t < 12; t++)
                if (!used[t] && exc2[t] > bv) { bv = exc2[t]; bi = t; }
            used[bi] = true;
            j4[r] = bi;
        }
    }
    __syncthreads();

    if (tid < 14) {
        mbuf[tid] = 0.25f * (out2[j4[0] * 14 + tid] + out2[j4[1] * 14 + tid] +
                             out2[j4[2] * 14 + tid] + out2[j4[3] * 14 + tid]);
    }
    __syncthreads();

    if (tid == 0) {
        float s = bd[0];
        #pragma unroll
        for (int c = 0; c < 14; c++) s += mbuf[c] * Wd[c];
        g_part[b] = s;
    }
}

// ---------------------------------------------------------------------------
// Kernel C: deterministic reduction of 256 partials -> mean -> sigmoid
// ---------------------------------------------------------------------------
__global__ void reduce_kernel(float* __restrict__ out) {
    __shared__ float sv[256];
    int tid = threadIdx.x;
    sv[tid] = g_part[tid];
    __syncthreads();
    for (int s = 128; s > 0; s >>= 1) {
        if (tid < s) sv[tid] += sv[tid + s];
        __syncthreads();
    }
    if (tid == 0) {
        float mval = sv[0] * (1.f / 256.f);
        out[0] = 1.f / (1.f + expf(-mval));
    }
}

// ---------------------------------------------------------------------------
extern "C" void kernel_launch(void* const* d_in, const int* in_sizes, int n_in,
                              void* d_out, int out_size) {
    const int*   x    = (const int*)  d_in[0];
    const float* emb  = (const float*)d_in[1];
    const float* W1   = (const float*)d_in[2];
    const float* b1   = (const float*)d_in[3];
    const float* W2   = (const float*)d_in[4];
    const float* b2   = (const float*)d_in[5];
    const float* Wd   = (const float*)d_in[6];
    const float* bd   = (const float*)d_in[7];
    float* out = (float*)d_out;

    // Kernel B dynamic smem: 14336+2056+256+256+8+96+168+12+4+14 floats
    const size_t smem = (14336 + 2056 + 256 + 256 + 8 + 96 + 168 + 12 + 4 + 14)
                        * sizeof(float);
    static bool attr_set = false;
    // (idempotent host-side attribute set; not a stream op, capture-safe)
    cudaFuncSetAttribute(dcnn_row_kernel,
                         cudaFuncAttributeMaxDynamicSharedMemorySize,
                         (int)smem);

    buildT_kernel<<<(VOCAB + 255) / 256, 256>>>(emb, W1);
    dcnn_row_kernel<<<B, 256, smem>>>(x, emb, W1, b1, W2, b2, Wd, bd);
    reduce_kernel<<<1, 256>>>(out);
    (void)attr_set; (void)in_sizes; (void)n_in; (void)out_size;
}

// round 3
// speedup vs baseline: 1.3683x; 1.3683x over previous
#include <cuda_runtime.h>
#include <math.h>

#define VOCAB 50000
#define EMB 50
#define B 256
#define S 2048
#define L1OUT (S + 6)      // 2054 conv1 output length
#define NEG_INF (-1e30f)

// Scratch (device globals: the allowed scratch mechanism)
__device__ __align__(16) float g_T[VOCAB * 8];  // T[v][0..6] = dot(emb[v], wmean[kw])
__device__ float g_part[B];                      // per-batch-row dense output
__device__ unsigned g_ctr = 0;                   // last-CTA counter (wraps -> self-reset)

// ---------------------------------------------------------------------------
// Kernel A: T[v][kw] = dot(emb[v], wmean[kw]). Tiled: 256 vocab rows per CTA,
// emb staged into smem with fully coalesced loads (stride-51 pad).
// ---------------------------------------------------------------------------
__global__ void __launch_bounds__(256) buildT_kernel(
    const float* __restrict__ emb, const float* __restrict__ W1) {
    extern __shared__ float dsm[];
    float* se = dsm;              // 256 * 51 floats
    float* wm = se + 256 * 51;    // 350 floats

    const int tid = threadIdx.x;
    const int base = blockIdx.x * 256;

    for (int i = tid; i < 350; i += 256) {
        float s = 0.f;
        #pragma unroll
        for (int c = 0; c < 6; c++) s += W1[i * 6 + c];
        wm[i] = s * (1.f / 6.f);
    }

    // Coalesced staging: linear over the 256x50 tile
    for (int i = tid; i < 256 * EMB; i += 256) {
        int row = i / EMB;
        int col = i - row * EMB;
        int v = base + row;
        se[row * 51 + col] = (v < VOCAB) ? emb[(size_t)v * EMB + col] : 0.f;
    }
    __syncthreads();

    int v = base + tid;
    if (v >= VOCAB) return;
    const float* er = se + tid * 51;   // stride 51 -> conflict-free across lanes
    float acc[7] = {0.f, 0.f, 0.f, 0.f, 0.f, 0.f, 0.f};
    #pragma unroll 10
    for (int cin = 0; cin < EMB; cin++) {
        float e = er[cin];
        #pragma unroll
        for (int kw = 0; kw < 7; kw++) acc[kw] += e * wm[kw * EMB + cin];
    }
    float4* d = (float4*)(g_T + (size_t)v * 8);
    d[0] = make_float4(acc[0], acc[1], acc[2], acc[3]);
    d[1] = make_float4(acc[4], acc[5], acc[6], 0.f);
}

// ---------------------------------------------------------------------------
// Kernel B: one CTA (512 thr) per batch row; fused final reduction (last CTA).
// ---------------------------------------------------------------------------
__global__ void __launch_bounds__(512) dcnn_row_kernel(
    const int*   __restrict__ x,
    const float* __restrict__ emb,
    const float* __restrict__ W1, const float* __restrict__ b1,
    const float* __restrict__ W2, const float* __restrict__ b2,
    const float* __restrict__ Wd, const float* __restrict__ bd,
    float* __restrict__ out) {

    extern __shared__ float sm[];
    float* sT   = sm;                 // 14336 floats (T per token, stride 7)
    float* exc  = sT + 14336;         // 2056
    float* red  = exc + 2056;         // 16
    int*   redi = (int*)(red + 16);   // 16
    int*   idx8 = redi + 16;          // 8
    float* s1p  = (float*)(idx8 + 8); // 96 (16x6, zero-padded)
    float* out2 = s1p + 96;           // 168 (12x14)
    float* exc2 = out2 + 168;         // 12
    int*   j4   = (int*)(exc2 + 12);  // 4
    float* mbuf = (float*)(j4 + 4);   // 14
    int*   tok8 = (int*)(mbuf + 14);  // 56
    int*   lastf= tok8 + 56;          // 1
    float* sW1  = sT;                 // alias after phase 3 (2100 floats)

    const int tid  = threadIdx.x;
    const int lane = tid & 31;
    const int wid  = tid >> 5;
    const int b    = blockIdx.x;
    const int* xr  = x + (size_t)b * S;

    // ---- Phase 1: stage T rows (stride-7 in smem: conflict-free)
    #pragma unroll
    for (int p = tid; p < S; p += 512) {
        int tok = xr[p];
        const float4* tp = (const float4*)(g_T + (size_t)tok * 8);
        float4 a = tp[0];
        float4 c = tp[1];
        float* d = sT + p * 7;
        d[0] = a.x; d[1] = a.y; d[2] = a.z; d[3] = a.w;
        d[4] = c.x; d[5] = c.y; d[6] = c.z;
    }
    __syncthreads();

    // ---- Phase 2: excitements
    for (int t = tid; t < L1OUT; t += 512) {
        float s = 0.f;
        int p0 = t - 6;
        #pragma unroll
        for (int kw = 0; kw < 7; kw++) {
            int p = p0 + kw;
            if (p >= 0 && p < S) s += sT[p * 7 + kw];
        }
        exc[t] = s;
    }
    __syncthreads();

    // ---- Phase 3: top-8 (descending, ties -> lower index) via shuffle reduce
    for (int r = 0; r < 8; r++) {
        float bv = NEG_INF; int bi = 0x7fffffff;
        #pragma unroll
        for (int t = tid; t < L1OUT; t += 512) {
            float v = exc[t];
            if (v > bv) { bv = v; bi = t; }   // ascending t: strict > keeps lowest idx
        }
        #pragma unroll
        for (int o = 16; o > 0; o >>= 1) {
            float v2 = __shfl_down_sync(0xffffffffu, bv, o);
            int   i2 = __shfl_down_sync(0xffffffffu, bi, o);
            if (v2 > bv || (v2 == bv && i2 < bi)) { bv = v2; bi = i2; }
        }
        if (lane == 0) { red[wid] = bv; redi[wid] = bi; }
        __syncthreads();
        if (wid == 0) {
            bv = (lane < 16) ? red[lane]  : NEG_INF;
            bi = (lane < 16) ? redi[lane] : 0x7fffffff;
            #pragma unroll
            for (int o = 8; o > 0; o >>= 1) {
                float v2 = __shfl_down_sync(0xffffffffu, bv, o);
                int   i2 = __shfl_down_sync(0xffffffffu, bi, o);
                if (v2 > bv || (v2 == bv && i2 < bi)) { bv = v2; bi = i2; }
            }
            if (lane == 0) { idx8[r] = bi; exc[bi] = NEG_INF; }
        }
        __syncthreads();
    }

    // ---- Phase 4: tokens + W1 staging; conv1 at 8 positions by 8 warps
    if (tid < 56) {
        int i = tid / 7, kw = tid - i * 7;
        int p = idx8[i] - 6 + kw;
        tok8[tid] = (p >= 0 && p < S) ? xr[p] : -1;
    }
    for (int i = tid; i < 2100; i += 512) sW1[i] = W1[i];
    if (tid < 96) s1p[tid] = 0.f;
    __syncthreads();

    if (wid < 8) {
        const int i = wid;   // pool position index
        float acc[6] = {0.f, 0.f, 0.f, 0.f, 0.f, 0.f};
        for (int rr = lane; rr < 350; rr += 32) {
            int kw = rr / EMB, cin = rr - kw * EMB;
            int t = tok8[i * 7 + kw];
            float e = (t >= 0) ? emb[(size_t)t * EMB + cin] : 0.f;
            #pragma unroll
            for (int c = 0; c < 6; c++) acc[c] += e * sW1[rr * 6 + c];
        }
        // Butterfly reduce: EVERY lane ends with the full (bit-identical) sum
        #pragma unroll
        for (int c = 0; c < 6; c++) {
            #pragma unroll
            for (int o = 16; o > 0; o >>= 1)
                acc[c] += __shfl_xor_sync(0xffffffffu, acc[c], o);
        }
        if (lane < 6)
            s1p[(4 + i) * 6 + lane] = 1.f / (1.f + expf(-(acc[lane] + b1[lane])));
    }
    __syncthreads();

    // ---- Phase 5: conv2 -> [12,14]
    if (tid < 12 * 14) {
        int t2 = tid / 14, c2 = tid - t2 * 14;
        float acc = b2[c2];
        #pragma unroll
        for (int kw2 = 0; kw2 < 5; kw2++)
            #pragma unroll
            for (int cin = 0; cin < 6; cin++)
                acc += s1p[(t2 + kw2) * 6 + cin] * W2[(kw2 * 6 + cin) * 14 + c2];
        out2[t2 * 14 + c2] = acc;
    }
    __syncthreads();

    if (tid < 12) {
        float s = 0.f;
        #pragma unroll
        for (int c = 0; c < 14; c++) s += out2[tid * 14 + c];
        exc2[tid] = s;
    }
    __syncthreads();

    if (tid == 0) {
        bool used[12];
        #pragma unroll
        for (int t = 0; t < 12; t++) used[t] = false;
        for (int r = 0; r < 4; r++) {
            float bv = NEG_INF; int bi = 0;
            for (int t = 0; t < 12; t++)
                if (!used[t] && exc2[t] > bv) { bv = exc2[t]; bi = t; }
            used[bi] = true;
            j4[r] = bi;
        }
    }
    __syncthreads();

    if (tid < 14) {
        mbuf[tid] = 0.25f * (out2[j4[0] * 14 + tid] + out2[j4[1] * 14 + tid] +
                             out2[j4[2] * 14 + tid] + out2[j4[3] * 14 + tid]);
    }
    __syncthreads();

    if (tid == 0) {
        float s = bd[0];
        #pragma unroll
        for (int c = 0; c < 14; c++) s += mbuf[c] * Wd[c];
        g_part[b] = s;
        __threadfence();
        unsigned old = atomicInc(&g_ctr, B - 1);   // wraps to 0 -> self-resets
        lastf[0] = (old == B - 1) ? 1 : 0;
    }
    __syncthreads();

    // ---- Last CTA: deterministic fixed-order reduction -> mean -> sigmoid
    if (lastf[0] && wid == 0) {
        float s = 0.f;
        #pragma unroll
        for (int i = lane; i < B; i += 32) s += g_part[i];
        #pragma unroll
        for (int o = 16; o > 0; o >>= 1) s += __shfl_down_sync(0xffffffffu, s, o);
        if (lane == 0) out[0] = 1.f / (1.f + expf(-(s * (1.f / 256.f))));
    }
}

// ---------------------------------------------------------------------------
extern "C" void kernel_launch(void* const* d_in, const int* in_sizes, int n_in,
                              void* d_out, int out_size) {
    const int*   x    = (const int*)  d_in[0];
    const float* emb  = (const float*)d_in[1];
    const float* W1   = (const float*)d_in[2];
    const float* b1   = (const float*)d_in[3];
    const float* W2   = (const float*)d_in[4];
    const float* b2   = (const float*)d_in[5];
    const float* Wd   = (const float*)d_in[6];
    const float* bd   = (const float*)d_in[7];
    float* out = (float*)d_out;

    const size_t smemA = (256 * 51 + 350) * sizeof(float);           // 53624 B
    const size_t smemB = (14336 + 2056 + 16 + 16 + 8 + 96 + 168 + 12
                          + 4 + 14 + 56 + 4) * sizeof(float);        // ~67 KB
    cudaFuncSetAttribute(buildT_kernel,
                         cudaFuncAttributeMaxDynamicSharedMemorySize, (int)smemA);
    cudaFuncSetAttribute(dcnn_row_kernel,
                         cudaFuncAttributeMaxDynamicSharedMemorySize, (int)smemB);

    buildT_kernel<<<(VOCAB + 255) / 256, 256, smemA>>>(emb, W1);
    dcnn_row_kernel<<<B, 512, smemB>>>(x, emb, W1, b1, W2, b2, Wd, bd, out);
    (void)in_sizes; (void)n_in; (void)out_size;
}

// round 4
// speedup vs baseline: 1.5603x; 1.1404x over previous
#include <cuda_runtime.h>
#include <math.h>

#define VOCAB 50000
#define EMB 50
#define B 256
#define S 2048
#define L1OUT (S + 6)      // 2054 conv1 output length
#define NEG_INF (-1e30f)
#define FULL 0xffffffffu

// Scratch (device globals: the allowed scratch mechanism)
__device__ __align__(16) float g_T[VOCAB * 8];  // T[v][0..6] = dot(emb[v], wmean[kw])
__device__ float g_part[B];                      // per-batch-row dense output
__device__ unsigned g_ctr = 0;                   // last-CTA counter (wraps -> self-reset)

// ---------------------------------------------------------------------------
// Kernel A: T[v][kw] = dot(emb[v], wmean[kw]). 256 vocab rows per CTA,
// emb staged into smem coalesced (stride-51 pad).
// ---------------------------------------------------------------------------
__global__ void __launch_bounds__(256) buildT_kernel(
    const float* __restrict__ emb, const float* __restrict__ W1) {
    extern __shared__ float dsm[];
    float* se = dsm;              // 256 * 51 floats
    float* wm = se + 256 * 51;    // 350 floats

    const int tid = threadIdx.x;
    const int base = blockIdx.x * 256;

    for (int i = tid; i < 350; i += 256) {
        float s = 0.f;
        #pragma unroll
        for (int c = 0; c < 6; c++) s += W1[i * 6 + c];
        wm[i] = s * (1.f / 6.f);
    }
    for (int i = tid; i < 256 * EMB; i += 256) {
        int row = i / EMB;
        int col = i - row * EMB;
        int v = base + row;
        se[row * 51 + col] = (v < VOCAB) ? emb[(size_t)v * EMB + col] : 0.f;
    }
    __syncthreads();

    int v = base + tid;
    if (v >= VOCAB) return;
    const float* er = se + tid * 51;
    float acc[7] = {0.f, 0.f, 0.f, 0.f, 0.f, 0.f, 0.f};
    #pragma unroll 10
    for (int cin = 0; cin < EMB; cin++) {
        float e = er[cin];
        #pragma unroll
        for (int kw = 0; kw < 7; kw++) acc[kw] += e * wm[kw * EMB + cin];
    }
    float4* d = (float4*)(g_T + (size_t)v * 8);
    d[0] = make_float4(acc[0], acc[1], acc[2], acc[3]);
    d[1] = make_float4(acc[4], acc[5], acc[6], 0.f);
}

// ---------------------------------------------------------------------------
// Kernel B: one CTA (512 thr) per batch row; 5 block barriers total;
// warp-0 tail; fused last-CTA final reduction.
// ---------------------------------------------------------------------------
__global__ void __launch_bounds__(512, 2) dcnn_row_kernel(
    const int*   __restrict__ x,
    const float* __restrict__ emb,
    const float* __restrict__ W1, const float* __restrict__ b1,
    const float* __restrict__ W2, const float* __restrict__ b2,
    const float* __restrict__ Wd, const float* __restrict__ bd,
    float* __restrict__ out) {

    extern __shared__ float sm[];
    float* sT     = sm;                    // 14336 (aliased by sW1 = 2100 later)
    float* cand_v = sT + 14336;            // 128
    int*   cand_i = (int*)(cand_v + 128);  // 128
    int*   idx8s  = cand_i + 128;          // 8
    float* s1p    = (float*)(idx8s + 8);   // 96 (16x6 zero-padded)
    float* out2s  = s1p + 96;              // 168 (12x14)
    float* exc2s  = out2s + 168;           // 12
    int*   j4s    = (int*)(exc2s + 12);    // 4
    float* sW1    = sT;                    // alias (sT dead after phase 2)

    const int tid  = threadIdx.x;
    const int lane = tid & 31;
    const int wid  = tid >> 5;
    const int b    = blockIdx.x;
    const int* xr  = x + (size_t)b * S;

    if (tid < 96) s1p[tid] = 0.f;

    // ---- Phase 1: stage T rows (stride-7 smem: conflict-free)
    #pragma unroll
    for (int k = 0; k < 4; k++) {
        int p = tid + k * 512;
        int tok = xr[p];
        const float4* tp = (const float4*)(g_T + (size_t)tok * 8);
        float4 a = tp[0];
        float4 c = tp[1];
        float* d = sT + p * 7;
        d[0] = a.x; d[1] = a.y; d[2] = a.z; d[3] = a.w;
        d[4] = c.x; d[5] = c.y; d[6] = c.z;
    }
    __syncthreads();                                        // barrier 1

    // ---- Phase 2: excitements straight into registers
    float ev[5];
    #pragma unroll
    for (int k = 0; k < 5; k++) {
        int t = tid + k * 512;
        float s = NEG_INF;
        if (t < L1OUT) {
            s = 0.f;
            #pragma unroll
            for (int kw = 0; kw < 7; kw++) {
                int p = t - 6 + kw;
                if ((unsigned)p < (unsigned)S) s += sT[p * 7 + kw];
            }
        }
        ev[k] = s;
    }
    __syncthreads();                                        // barrier 2 (sT dead)

    // W1 prefetch into regs (latency hidden behind shuffle rounds below)
    float w1r[5];
    #pragma unroll
    for (int k = 0; k < 5; k++) {
        int i = tid + k * 512;
        w1r[k] = (i < 2100) ? W1[i] : 0.f;
    }

    // ---- Phase 3a: warp-local top-8 (no barriers)
    #pragma unroll
    for (int r = 0; r < 8; r++) {
        float bv = NEG_INF; int bi = 0x7fffffff;
        #pragma unroll
        for (int k = 0; k < 5; k++)
            if (ev[k] > bv) { bv = ev[k]; bi = tid + k * 512; }  // k asc -> lowest t on tie
        #pragma unroll
        for (int o = 16; o > 0; o >>= 1) {
            float v2 = __shfl_down_sync(FULL, bv, o);
            int   i2 = __shfl_down_sync(FULL, bi, o);
            if (v2 > bv || (v2 == bv && i2 < bi)) { bv = v2; bi = i2; }
        }
        bv = __shfl_sync(FULL, bv, 0);
        bi = __shfl_sync(FULL, bi, 0);
        #pragma unroll
        for (int k = 0; k < 5; k++)
            if (tid + k * 512 == bi) ev[k] = NEG_INF;       // kill winner
        if (lane == 0) { cand_v[wid * 8 + r] = bv; cand_i[wid * 8 + r] = bi; }
    }
    #pragma unroll
    for (int k = 0; k < 5; k++) {                           // store staged W1
        int i = tid + k * 512;
        if (i < 2100) sW1[i] = w1r[k];
    }
    __syncthreads();                                        // barrier 3

    // ---- Phase 3b: warp 0 merges 128 candidates -> global top-8 in order
    if (wid == 0) {
        float cv[4]; int ci[4];
        #pragma unroll
        for (int j = 0; j < 4; j++) {
            cv[j] = cand_v[lane + 32 * j];
            ci[j] = cand_i[lane + 32 * j];
        }
        #pragma unroll
        for (int r = 0; r < 8; r++) {
            float bv = NEG_INF; int bi = 0x7fffffff;
            #pragma unroll
            for (int j = 0; j < 4; j++)
                if (cv[j] > bv || (cv[j] == bv && ci[j] < bi)) { bv = cv[j]; bi = ci[j]; }
            #pragma unroll
            for (int o = 16; o > 0; o >>= 1) {
                float v2 = __shfl_down_sync(FULL, bv, o);
                int   i2 = __shfl_down_sync(FULL, bi, o);
                if (v2 > bv || (v2 == bv && i2 < bi)) { bv = v2; bi = i2; }
            }
            bv = __shfl_sync(FULL, bv, 0);
            bi = __shfl_sync(FULL, bi, 0);
            #pragma unroll
            for (int j = 0; j < 4; j++)
                if (ci[j] == bi) cv[j] = NEG_INF;
            if (lane == 0) idx8s[r] = bi;
        }
    }
    __syncthreads();                                        // barrier 4

    // ---- Phase 4: conv1 at the 8 selected positions (warp i -> position i)
    if (wid < 8) {
        int pos = idx8s[wid];
        int tkn = -1;
        if (lane < 7) {
            int p = pos - 6 + lane;
            tkn = ((unsigned)p < (unsigned)S) ? xr[p] : -1;
        }
        float acc[6] = {0.f, 0.f, 0.f, 0.f, 0.f, 0.f};
        #pragma unroll
        for (int k = 0; k < 11; k++) {
            int rr = lane + 32 * k;
            bool ok = rr < 350;
            int rr2 = ok ? rr : 0;
            int kw = rr2 / 50;
            int cin = rr2 - kw * 50;
            int t = __shfl_sync(FULL, tkn, kw);
            float e = (ok && t >= 0) ? emb[(size_t)t * EMB + cin] : 0.f;
            #pragma unroll
            for (int c = 0; c < 6; c++) acc[c] += e * sW1[rr2 * 6 + c];
        }
        // butterfly: every lane gets the full bit-identical sums
        #pragma unroll
        for (int c = 0; c < 6; c++) {
            #pragma unroll
            for (int o = 16; o > 0; o >>= 1)
                acc[c] += __shfl_xor_sync(FULL, acc[c], o);
        }
        if (lane < 6) {
            float a = acc[0];
            a = (lane == 1) ? acc[1] : a;
            a = (lane == 2) ? acc[2] : a;
            a = (lane == 3) ? acc[3] : a;
            a = (lane == 4) ? acc[4] : a;
            a = (lane == 5) ? acc[5] : a;
            s1p[(4 + wid) * 6 + lane] = 1.f / (1.f + expf(-(a + b1[lane])));
        }
    }
    __syncthreads();                                        // barrier 5 (last)

    // ---- Tail: warp 0 only, __syncwarp granularity
    if (wid == 0) {
        // conv2 -> out2s[12x14]
        #pragma unroll
        for (int j = 0; j < 6; j++) {
            int idx = lane + 32 * j;
            if (idx < 168) {
                int t2 = idx / 14, c2 = idx - t2 * 14;
                float a = b2[c2];
                #pragma unroll
                for (int kw2 = 0; kw2 < 5; kw2++)
                    #pragma unroll
                    for (int cin = 0; cin < 6; cin++)
                        a += s1p[(t2 + kw2) * 6 + cin] * W2[(kw2 * 6 + cin) * 14 + c2];
                out2s[idx] = a;
            }
        }
        __syncwarp();
        if (lane < 12) {
            float s = 0.f;
            #pragma unroll
            for (int c = 0; c < 14; c++) s += out2s[lane * 14 + c];
            exc2s[lane] = s;
        }
        __syncwarp();
        if (lane == 0) {
            bool used[12];
            #pragma unroll
            for (int t = 0; t < 12; t++) used[t] = false;
            for (int r = 0; r < 4; r++) {
                float bv = NEG_INF; int bi = 0;
                for (int t = 0; t < 12; t++)
                    if (!used[t] && exc2s[t] > bv) { bv = exc2s[t]; bi = t; }
                used[bi] = true;
                j4s[r] = bi;
            }
        }
        __syncwarp();
        float m = 0.f;
        if (lane < 14)
            m = 0.25f * (out2s[j4s[0] * 14 + lane] + out2s[j4s[1] * 14 + lane] +
                         out2s[j4s[2] * 14 + lane] + out2s[j4s[3] * 14 + lane]) * Wd[lane];
        #pragma unroll
        for (int o = 16; o > 0; o >>= 1) m += __shfl_xor_sync(FULL, m, o);

        unsigned old = 0;
        if (lane == 0) {
            g_part[b] = m + bd[0];
            __threadfence();
            old = atomicInc(&g_ctr, B - 1);                 // wraps -> self-reset
        }
        old = __shfl_sync(FULL, old, 0);
        if (old == B - 1) {
            __threadfence();                                // acquire side
            float s = 0.f;
            #pragma unroll
            for (int k = 0; k < 8; k++) s += g_part[lane + 32 * k];
            #pragma unroll
            for (int o = 16; o > 0; o >>= 1) s += __shfl_xor_sync(FULL, s, o);
            if (lane == 0) out[0] = 1.f / (1.f + expf(-(s * (1.f / 256.f))));
        }
    }
}

// ---------------------------------------------------------------------------
extern "C" void kernel_launch(void* const* d_in, const int* in_sizes, int n_in,
                              void* d_out, int out_size) {
    const int*   x    = (const int*)  d_in[0];
    const float* emb  = (const float*)d_in[1];
    const float* W1   = (const float*)d_in[2];
    const float* b1   = (const float*)d_in[3];
    const float* W2   = (const float*)d_in[4];
    const float* b2   = (const float*)d_in[5];
    const float* Wd   = (const float*)d_in[6];
    const float* bd   = (const float*)d_in[7];
    float* out = (float*)d_out;

    const size_t smemA = (256 * 51 + 350) * sizeof(float);                 // 53624 B
    const size_t smemB = (14336 + 128 + 128 + 8 + 96 + 168 + 12 + 4)
                         * sizeof(float);                                  // 59520 B
    cudaFuncSetAttribute(buildT_kernel,
                         cudaFuncAttributeMaxDynamicSharedMemorySize, (int)smemA);
    cudaFuncSetAttribute(dcnn_row_kernel,
                         cudaFuncAttributeMaxDynamicSharedMemorySize, (int)smemB);

    buildT_kernel<<<(VOCAB + 255) / 256, 256, smemA>>>(emb, W1);
    dcnn_row_kernel<<<B, 512, smemB>>>(x, emb, W1, b1, W2, b2, Wd, bd, out);
    (void)in_sizes; (void)n_in; (void)out_size;
}

// round 5
// speedup vs baseline: 1.6624x; 1.0654x over previous
#include <cuda_runtime.h>
#include <math.h>

#define VOCAB 50000
#define EMB 50
#define B 256
#define S 2048
#define L1OUT (S + 6)      // 2054 conv1 output length
#define FULL 0xffffffffu

// Scratch (device globals: the allowed scratch mechanism)
__device__ __align__(16) float g_T[VOCAB * 8];  // T[v][0..6] = dot(emb[v], wmean[kw])
__device__ float g_part[B];                      // per-batch-row dense output
__device__ unsigned g_ctr = 0;                   // last-CTA counter (wraps -> self-reset)

// Order-preserving float -> u32 map (u32 compare == float compare)
__device__ __forceinline__ unsigned fmono(float f) {
    unsigned u = __float_as_uint(f);
    return (u & 0x80000000u) ? ~u : (u | 0x80000000u);
}

// ---------------------------------------------------------------------------
// Kernel A: T[v][kw] = dot(emb[v], wmean[kw]). 128 vocab rows per CTA,
// float2-vectorized coalesced staging into smem (stride-51: conflict-free).
// ---------------------------------------------------------------------------
__global__ void __launch_bounds__(128) buildT_kernel(
    const float* __restrict__ emb, const float* __restrict__ W1) {
    __shared__ float se[128 * 51];
    __shared__ float wm[7 * 50];

    const int tid  = threadIdx.x;
    const int base = blockIdx.x * 128;
    const int nrows = min(128, VOCAB - base);

    for (int i = tid; i < 350; i += 128) {
        float s = 0.f;
        #pragma unroll
        for (int c = 0; c < 6; c++) s += W1[i * 6 + c];
        wm[i] = s * (1.f / 6.f);
    }
    // emb rows are 200B (8B-aligned) -> float2 loads are safe
    const float2* e2 = (const float2*)(emb + (size_t)base * EMB);
    for (int i = tid; i < nrows * 25; i += 128) {
        int row = i / 25;
        int c2  = i - row * 25;
        float2 v = e2[row * 25 + c2];
        se[row * 51 + 2 * c2]     = v.x;
        se[row * 51 + 2 * c2 + 1] = v.y;
    }
    __syncthreads();

    if (tid >= nrows) return;
    const float* er = se + tid * 51;
    float acc[7] = {0.f, 0.f, 0.f, 0.f, 0.f, 0.f, 0.f};
    #pragma unroll 10
    for (int cin = 0; cin < EMB; cin++) {
        float e = er[cin];
        #pragma unroll
        for (int kw = 0; kw < 7; kw++) acc[kw] += e * wm[kw * EMB + cin];
    }
    float4* d = (float4*)(g_T + (size_t)(base + tid) * 8);
    d[0] = make_float4(acc[0], acc[1], acc[2], acc[3]);
    d[1] = make_float4(acc[4], acc[5], acc[6], 0.f);
}

// ---------------------------------------------------------------------------
// Kernel B: one CTA (512 thr) per batch row. Cooperative 8-lane T gather,
// REDUX-based top-8, warp-0 tail, fused last-CTA final reduction.
// ---------------------------------------------------------------------------
__global__ void __launch_bounds__(512, 2) dcnn_row_kernel(
    const int*   __restrict__ x,
    const float* __restrict__ emb,
    const float* __restrict__ W1, const float* __restrict__ b1,
    const float* __restrict__ W2, const float* __restrict__ b2,
    const float* __restrict__ Wd, const float* __restrict__ bd,
    float* __restrict__ out) {

    extern __shared__ float sm[];
    int*      stok   = (int*)sm;                 // 2048 tokens
    float*    sT     = sm + 2048;                // 14336 (stride-7 T values)
    unsigned* cand_u = (unsigned*)(sT + 14336);  // 128
    int*      cand_t = (int*)(cand_u + 128);     // 128
    int*      idx8s  = cand_t + 128;             // 8
    float*    s1p    = (float*)(idx8s + 8);      // 96 (16x6 zero-padded)
    float*    out2s  = s1p + 96;                 // 168 (12x14)
    float*    sW1    = sT;                       // alias (sT dead after phase 2)

    const int tid  = threadIdx.x;
    const int lane = tid & 31;
    const int wid  = tid >> 5;
    const int b    = blockIdx.x;
    const int* xr  = x + (size_t)b * S;

    if (tid < 96) s1p[tid] = 0.f;

    // ---- Phase 1: per-warp token staging + cooperative 8-lane T gather
    const int wbase = wid << 7;                  // 128 rows per warp
    #pragma unroll
    for (int k = 0; k < 4; k++) {
        int r = wbase + (k << 5) + lane;
        stok[r] = xr[r];
    }
    __syncwarp();
    const int col = lane & 7;
    const int rsub = lane >> 3;
    #pragma unroll 8
    for (int j = 0; j < 32; j++) {
        int row = wbase + (j << 2) + rsub;
        int tokr = stok[row];
        float v = g_T[(size_t)tokr * 8 + col];
        if (col < 7) sT[row * 7 + col] = v;      // 28 consecutive addrs: no conflicts
    }
    __syncthreads();                              // barrier 1: sT ready

    // ---- Phase 2: excitements -> monotone u32 in registers
    unsigned evu[5];
    #pragma unroll
    for (int k = 0; k < 5; k++) {
        int t = tid + k * 512;
        unsigned u = 0u;
        if (t < L1OUT) {
            float s = 0.f;
            #pragma unroll
            for (int kw = 0; kw < 7; kw++) {
                int p = t - 6 + kw;
                if ((unsigned)p < (unsigned)S) s += sT[p * 7 + kw];
            }
            u = fmono(s);
        }
        evu[k] = u;
    }
    __syncthreads();                              // barrier 2: sT dead

    // W1 prefetch into regs (hidden behind the redux rounds)
    float w1r[5];
    #pragma unroll
    for (int k = 0; k < 5; k++) {
        int i = tid + k * 512;
        w1r[k] = (i < 2100) ? W1[i] : 0.f;
    }

    // ---- Phase 3a: warp-local top-8 via REDUX (value desc, index asc on ties)
    #pragma unroll
    for (int r = 0; r < 8; r++) {
        unsigned bu = 0u; int bt = 0x7fffffff; int bk = 0;
        #pragma unroll
        for (int k = 0; k < 5; k++)
            if (evu[k] > bu) { bu = evu[k]; bt = tid + k * 512; bk = k; }  // k asc -> lowest t
        unsigned m = __reduce_max_sync(FULL, bu);
        int tw = (bu == m) ? bt : 0x7fffffff;
        int tmin = __reduce_min_sync(FULL, tw);
        bool win = (bu == m) && (bt == tmin);
        #pragma unroll
        for (int k = 0; k < 5; k++)
            if (win && k == bk) evu[k] = 0u;
        if (lane == 0) { cand_u[wid * 8 + r] = m; cand_t[wid * 8 + r] = tmin; }
    }
    #pragma unroll
    for (int k = 0; k < 5; k++) {                 // store staged W1
        int i = tid + k * 512;
        if (i < 2100) sW1[i] = w1r[k];
    }
    __syncthreads();                              // barrier 3

    // ---- Phase 3b: warp 0 merges 128 candidates -> global top-8 (ordered)
    if (wid == 0) {
        unsigned cu[4]; int ct[4];
        #pragma unroll
        for (int j = 0; j < 4; j++) {
            cu[j] = cand_u[lane + 32 * j];
            ct[j] = cand_t[lane + 32 * j];
        }
        #pragma unroll
        for (int r = 0; r < 8; r++) {
            unsigned bu = 0u; int bt = 0x7fffffff; int bj = 0;
            #pragma unroll
            for (int j = 0; j < 4; j++)
                if (cu[j] > bu || (cu[j] == bu && ct[j] < bt)) {
                    bu = cu[j]; bt = ct[j]; bj = j;
                }
            unsigned m = __reduce_max_sync(FULL, bu);
            int tw = (bu == m) ? bt : 0x7fffffff;
            int tmin = __reduce_min_sync(FULL, tw);
            bool win = (bu == m) && (bt == tmin);
            #pragma unroll
            for (int j = 0; j < 4; j++)
                if (win && j == bj) cu[j] = 0u;
            if (lane == 0) idx8s[r] = tmin;
        }
    }
    __syncthreads();                              // barrier 4

    // ---- Phase 4: conv1 at the 8 selected positions (warp i -> position i)
    if (wid < 8) {
        int pos = idx8s[wid];
        int tkn = -1;
        if (lane < 7) {
            int p = pos - 6 + lane;
            tkn = ((unsigned)p < (unsigned)S) ? stok[p] : -1;
        }
        float acc[6] = {0.f, 0.f, 0.f, 0.f, 0.f, 0.f};
        #pragma unroll
        for (int k = 0; k < 11; k++) {
            int rr = lane + 32 * k;
            bool ok = rr < 350;
            int rr2 = ok ? rr : 0;
            int kw = rr2 / 50;
            int cin = rr2 - kw * 50;
            int t = __shfl_sync(FULL, tkn, kw);
            float e = (ok && t >= 0) ? emb[(size_t)t * EMB + cin] : 0.f;
            #pragma unroll
            for (int c = 0; c < 6; c++) acc[c] += e * sW1[rr2 * 6 + c];
        }
        #pragma unroll
        for (int c = 0; c < 6; c++) {
            #pragma unroll
            for (int o = 16; o > 0; o >>= 1)
                acc[c] += __shfl_xor_sync(FULL, acc[c], o);   // all lanes: full sum
        }
        if (lane < 6) {
            float a = acc[0];
            a = (lane == 1) ? acc[1] : a;
            a = (lane == 2) ? acc[2] : a;
            a = (lane == 3) ? acc[3] : a;
            a = (lane == 4) ? acc[4] : a;
            a = (lane == 5) ? acc[5] : a;
            s1p[(4 + wid) * 6 + lane] = 1.f / (1.f + expf(-(a + b1[lane])));
        }
    }
    __syncthreads();                              // barrier 5 (last)

    // ---- Tail: warp 0 only
    if (wid == 0) {
        // conv2 -> out2s[12x14]
        #pragma unroll
        for (int j = 0; j < 6; j++) {
            int idx = lane + 32 * j;
            if (idx < 168) {
                int t2 = idx / 14, c2 = idx - t2 * 14;
                float a = b2[c2];
                #pragma unroll
                for (int kw2 = 0; kw2 < 5; kw2++)
                    #pragma unroll
                    for (int cin = 0; cin < 6; cin++)
                        a += s1p[(t2 + kw2) * 6 + cin] * W2[(kw2 * 6 + cin) * 14 + c2];
                out2s[idx] = a;
            }
        }
        __syncwarp();
        // top-4 of channel-sums via REDUX (lane t2 owns row t2)
        float e2 = 0.f;
        if (lane < 12) {
            #pragma unroll
            for (int c = 0; c < 14; c++) e2 += out2s[lane * 14 + c];
        }
        unsigned e2u = (lane < 12) ? fmono(e2) : 0u;
        int j4r[4];
        #pragma unroll
        for (int r = 0; r < 4; r++) {
            unsigned m = __reduce_max_sync(FULL, e2u);
            int tw = (e2u == m) ? lane : 63;
            int tmin = __reduce_min_sync(FULL, tw);
            j4r[r] = tmin;
            if (lane == tmin) e2u = 0u;
        }
        float mm = 0.f;
        if (lane < 14)
            mm = 0.25f * (out2s[j4r[0] * 14 + lane] + out2s[j4r[1] * 14 + lane] +
                          out2s[j4r[2] * 14 + lane] + out2s[j4r[3] * 14 + lane]) * Wd[lane];
        #pragma unroll
        for (int o = 16; o > 0; o >>= 1) mm += __shfl_xor_sync(FULL, mm, o);

        unsigned old = 0;
        if (lane == 0) {
            g_part[b] = mm + bd[0];
            __threadfence();
            old = atomicInc(&g_ctr, B - 1);       // wraps -> self-reset each replay
        }
        old = __shfl_sync(FULL, old, 0);
        if (old == B - 1) {
            __threadfence();                      // acquire side
            float s = 0.f;
            #pragma unroll
            for (int k = 0; k < 8; k++) s += g_part[lane + 32 * k];
            #pragma unroll
            for (int o = 16; o > 0; o >>= 1) s += __shfl_xor_sync(FULL, s, o);
            if (lane == 0) out[0] = 1.f / (1.f + expf(-(s * (1.f / 256.f))));
        }
    }
}

// ---------------------------------------------------------------------------
extern "C" void kernel_launch(void* const* d_in, const int* in_sizes, int n_in,
                              void* d_out, int out_size) {
    const int*   x    = (const int*)  d_in[0];
    const float* emb  = (const float*)d_in[1];
    const float* W1   = (const float*)d_in[2];
    const float* b1   = (const float*)d_in[3];
    const float* W2   = (const float*)d_in[4];
    const float* b2   = (const float*)d_in[5];
    const float* Wd   = (const float*)d_in[6];
    const float* bd   = (const float*)d_in[7];
    float* out = (float*)d_out;

    const size_t smemB = (2048 + 14336 + 128 + 128 + 8 + 96 + 168)
                         * sizeof(float);                                  // 67648 B
    cudaFuncSetAttribute(dcnn_row_kernel,
                         cudaFuncAttributeMaxDynamicSharedMemorySize, (int)smemB);

    buildT_kernel<<<(VOCAB + 127) / 128, 128>>>(emb, W1);
    dcnn_row_kernel<<<B, 512, smemB>>>(x, emb, W1, b1, W2, b2, Wd, bd, out);
    (void)in_sizes; (void)n_in; (void)out_size;
}